// round 11
// baseline (speedup 1.0000x reference)
#include <cuda_runtime.h>

// CRF NLL: B=1024, T=512, C=53, BOS=1, EOS=2
// TIME-PARALLEL forward (NCH=4 chunks/batch, Birkhoff burn-in splice) in
// 128-THREAD blocks: one block per batch, warp w = chunk w, so warps land on
// all 4 SMSPs (SMSP = wid%4). __launch_bounds__(128,3) -> 3 blocks/SM ->
// 3 warps/SMSP on the whole chip (R3's proven depth, 2x the silicon).
// Step = R3 recipe: 4-acc f32x2 dot, renorm-by-p[0] every 4, exp-at-use,
// dist-4 raw emission prefetch. Fused last-block reduction.

#define Bn   1024
#define Tn   512
#define Cn   53
#define BOSi 1
#define EOSi 2
#define NCH  4
#define BURN 10

__device__ float    g_chunk[Bn * NCH];
__device__ unsigned g_ticket;   // zero-init; reset by last block each launch

typedef unsigned long long ull;

__device__ __forceinline__ ull pack2(float a, float b) {
    ull r; asm("mov.b64 %0, {%1,%2};" : "=l"(r) : "f"(a), "f"(b)); return r;
}
__device__ __forceinline__ void unpack2(ull v, float& a, float& b) {
    asm("mov.b64 {%0,%1}, %2;" : "=f"(a), "=f"(b) : "l"(v));
}
__device__ __forceinline__ void fma2(ull& acc, ull a, ull b) {
    asm("fma.rn.f32x2 %0, %1, %2, %0;" : "+l"(acc) : "l"(a), "l"(b));
}
__device__ __forceinline__ ull add2(ull a, ull b) {
    ull r; asm("add.rn.f32x2 %0, %1, %2;" : "=l"(r) : "l"(a), "l"(b)); return r;
}
__device__ __forceinline__ void lds_v2u64(unsigned addr, ull& x, ull& y) {
    asm volatile("ld.shared.v2.u64 {%0,%1}, [%2];" : "=l"(x), "=l"(y) : "r"(addr));
}

// one forward step (R3 recipe): dot, optional renorm by p[0], *exp(em), store
#define CRF_STEP(E0, E1, REN) do {                                          \
    unsigned pa_ = pbase + (unsigned)buf * 256u;                            \
    ull aA0_=0, aA1_=0, aB0_=0, aB1_=0;                                     \
    _Pragma("unroll")                                                       \
    for (int k_ = 0; k_ < 14; k_++) {                                       \
        ull x_, y_;                                                         \
        lds_v2u64(pa_ + 16u * k_, x_, y_);                                  \
        fma2(aA0_, x_, eA[2*k_]);  fma2(aA1_, y_, eA[2*k_+1]);              \
        fma2(aB0_, x_, eB[2*k_]);  fma2(aB1_, y_, eB[2*k_+1]);              \
    }                                                                       \
    float u_, v_, sA_, sB_;                                                 \
    unpack2(add2(aA0_, aA1_), u_, v_); sA_ = u_ + v_;                       \
    unpack2(add2(aB0_, aB1_), u_, v_); sB_ = u_ + v_;                       \
    float r_ = 1.0f;                                                        \
    if (REN) {                                                              \
        float s_ = prow[buf * 64];                                          \
        r_ = __fdividef(1.0f, s_);                                          \
        L += __logf(s_);                                                    \
    }                                                                       \
    float n0_ = sA_ * r_ * __expf(E0);                                      \
    float n1_ = sB_ * r_ * __expf(E1);                                      \
    buf ^= 1;                                                               \
    *(float2*)(prow + buf * 64 + 2 * lane) = make_float2(n0_, n1_);         \
    __syncwarp();                                                           \
    p0 = n0_; p1 = n1_;                                                     \
} while (0)

// burst-load 4 steps of RAW emissions (clamped row; exp applied at use)
#define LOAD4(P0A, P1A, BASEROW) do {                                       \
    _Pragma("unroll")                                                       \
    for (int j_ = 0; j_ < 4; j_++) {                                        \
        int rr_ = (BASEROW) + j_; if (rr_ > Tn - 1) rr_ = Tn - 1;           \
        const float* rp_ = emb + (size_t)rr_ * Cn;                          \
        P0A[j_] = __ldg(rp_ + c0v);                                         \
        P1A[j_] = __ldg(rp_ + c1v);                                         \
    }                                                                       \
} while (0)

// run the recurrence for t in [T0, T1) with dist-4 double-buffered prefetch
#define RUN_RANGE(T0, T1) do {                                              \
    int base_ = (T0);                                                       \
    LOAD4(xa, xb, base_);                                                   \
    for (;;) {                                                              \
        if (base_ + 4 > (T1)) break;                                        \
        LOAD4(ya, yb, base_ + 4);                                           \
        CRF_STEP(xa[0], xb[0], ((base_ + 0) & 3) == 2);                     \
        CRF_STEP(xa[1], xb[1], ((base_ + 1) & 3) == 2);                     \
        CRF_STEP(xa[2], xb[2], ((base_ + 2) & 3) == 2);                     \
        CRF_STEP(xa[3], xb[3], ((base_ + 3) & 3) == 2);                     \
        base_ += 4;                                                         \
        if (base_ + 4 > (T1)) break;                                        \
        LOAD4(xa, xb, base_ + 4);                                           \
        CRF_STEP(ya[0], yb[0], ((base_ + 0) & 3) == 2);                     \
        CRF_STEP(ya[1], yb[1], ((base_ + 1) & 3) == 2);                     \
        CRF_STEP(ya[2], yb[2], ((base_ + 2) & 3) == 2);                     \
        CRF_STEP(ya[3], yb[3], ((base_ + 3) & 3) == 2);                     \
        base_ += 4;                                                         \
    }                                                                       \
    for (int t_ = base_; t_ < (T1); t_++) {                                 \
        float e0_ = __ldg(emb + (size_t)t_ * Cn + c0v);                     \
        float e1_ = __ldg(emb + (size_t)t_ * Cn + c1v);                     \
        CRF_STEP(e0_, e1_, (t_ & 3) == 2);                                  \
    }                                                                       \
} while (0)

__global__ void __launch_bounds__(128, 3)
crf_fwd_kernel(const float* __restrict__ em,
               const int*   __restrict__ tags,
               const float* __restrict__ mask,
               const float* __restrict__ trans,
               float* __restrict__ out)
{
    __shared__ float trs[Cn * Cn];
    __shared__ __align__(16) float p_sm[4][2][64];  // [warp][buf][slot]
    __shared__ float rsum[4];
    __shared__ int   slast;

    const int tid  = threadIdx.x;
    const int lane = tid & 31;
    const int w    = tid >> 5;      // warp = chunk 0..3 (covers SMSP 0..3)
    const int b    = blockIdx.x;    // batch
    const int ch   = w;

    for (int i = tid; i < Cn * Cn; i += 128) trs[i] = trans[i];
    __syncthreads();

    const int  c0  = 2 * lane,            c1  = 2 * lane + 1;
    const bool okA = (c0 < Cn);           const bool okB = (c1 < Cn);
    const int  c0v = okA ? c0 : (Cn - 1); const int  c1v = okB ? c1 : (Cn - 1);

    const float* emb = em + (size_t)b * Tn * Cn;
    const int*   tg  = tags + b * Tn;
    float* prow = &p_sm[w][0][0];
    const unsigned pbase = (unsigned)__cvta_generic_to_shared(prow);

    // ---- sequence length = sum(mask) ----
    float ms = 0.f;
    for (int i = lane; i < Tn; i += 32) ms += mask[b * Tn + i];
#pragma unroll
    for (int off = 16; off; off >>= 1) ms += __shfl_xor_sync(~0u, ms, off);
    const int tl = (int)ms;   // steps run for t in [2, tl)

    // ---- chunk boundaries within [2, tl) ----
    const int s  = 2 + ((tl - 2) * ch) / NCH;
    const int e  = 2 + ((tl - 2) * (ch + 1)) / NCH;
    const int bs = (ch == 0) ? s : (s - BURN);   // s >= 2+63 for ch>0

    // ---- packed exp(transition) columns for this lane's 2 output cols ----
    ull eA[28], eB[28];
#pragma unroll
    for (int k = 0; k < 28; k++) {
        int r0 = 2 * k, r1 = 2 * k + 1;
        float a0 = (okA && r0 < Cn) ? __expf(trs[r0 * Cn + c0]) : 0.f;
        float a1 = (okA && r1 < Cn) ? __expf(trs[r1 * Cn + c0]) : 0.f;
        float b0 = (okB && r0 < Cn) ? __expf(trs[r0 * Cn + c1]) : 0.f;
        float b1 = (okB && r1 < Cn) ? __expf(trs[r1 * Cn + c1]) : 0.f;
        eA[k] = pack2(a0, a1);
        eB[k] = pack2(b0, b1);
    }

    // ---- init ----
    float p0, p1;
    if (ch == 0) {   // exact alpha_1 in prob domain
        p0 = okA ? __expf(trs[BOSi * Cn + c0] + emb[Cn + c0]) : 0.f;
        p1 = okB ? __expf(trs[BOSi * Cn + c1] + emb[Cn + c1]) : 0.f;
    } else {         // uniform (burn-in contracts it to ~1e-9 direction err)
        p0 = okA ? 1.0f : 0.f;
        p1 = okB ? 1.0f : 0.f;
    }
    int buf = 0;
    *(float2*)(prow + 2 * lane) = make_float2(p0, p1);
    __syncwarp();

    float L = 0.f;
    float xa[4], xb[4], ya[4], yb[4];

    // ---- burn-in (ch>0) then boundary snapshot ----
    float Lb = 0.f, logBeta = 0.f;
    if (ch != 0) {
        RUN_RANGE(bs, s);
        Lb = L;
        float beta = p0 + p1;
#pragma unroll
        for (int off = 16; off; off >>= 1) beta += __shfl_xor_sync(~0u, beta, off);
        logBeta = __logf(beta);
    }

    // ---- owned segment ----
    RUN_RANGE(s, e);

    // ---- chunk contribution ----
    float endv;
    if (ch == NCH - 1) {
        endv = p0 * __expf(trs[c0v * Cn + EOSi]) + p1 * __expf(trs[c1v * Cn + EOSi]);
    } else {
        endv = p0 + p1;
    }
#pragma unroll
    for (int off = 16; off; off >>= 1) endv += __shfl_xor_sync(~0u, endv, off);
    float contrib = L - Lb - logBeta + __logf(endv);

    // ---- gold-path score slice for [s, e) ----
    float sc = 0.f;
    for (int t = s + lane; t < e; t += 32) {
        int a = tg[t - 1], c = tg[t];
        sc += emb[(size_t)t * Cn + c] + trs[a * Cn + c];
    }
#pragma unroll
    for (int off = 16; off; off >>= 1) sc += __shfl_xor_sync(~0u, sc, off);

    if (lane == 0) {
        if (ch == 0) {
            int t1 = tg[1];
            sc += trs[BOSi * Cn + t1] + emb[Cn + t1];
        }
        if (ch == NCH - 1) {
            int lt = tg[tl];   // tags at index == length
            sc += trs[lt * Cn + EOSi];
        }
        g_chunk[(b << 2) | ch] = contrib - sc;
    }

    // ---- fused reduction: last block sums all chunk contributions ----
    __threadfence();
    __syncthreads();
    if (tid == 0) {
        unsigned tk = atomicAdd(&g_ticket, 1u);
        slast = (tk == (unsigned)(gridDim.x - 1)) ? 1 : 0;
    }
    __syncthreads();
    if (slast) {
        __threadfence();
        float acc = 0.f;
        for (int i = tid; i < Bn * NCH; i += 128) acc += __ldcg(&g_chunk[i]);
#pragma unroll
        for (int off = 16; off; off >>= 1) acc += __shfl_xor_sync(~0u, acc, off);
        if (lane == 0) rsum[w] = acc;
        __syncthreads();
        if (tid == 0) {
            out[0] = rsum[0] + rsum[1] + rsum[2] + rsum[3];
            g_ticket = 0;   // reset for next graph replay
        }
    }
}

extern "C" void kernel_launch(void* const* d_in, const int* in_sizes, int n_in,
                              void* d_out, int out_size)
{
    const float* em    = (const float*)d_in[0];
    const int*   tags  = (const int*)  d_in[1];
    const float* mask  = (const float*)d_in[2];
    const float* trans = (const float*)d_in[3];
    float* out = (float*)d_out;

    crf_fwd_kernel<<<Bn, 128>>>(em, tags, mask, trans, out);
}

// round 12
// speedup vs baseline: 1.5698x; 1.5698x over previous
#include <cuda_runtime.h>

// CRF NLL: B=1024, T=512, C=53, BOS=1, EOS=2
// TIME-PARALLEL forward (NCH=4 chunks/batch, Birkhoff burn-in splice) in
// 128-THREAD blocks: one block per batch, warp w = chunk w, so warps land on
// all 4 SMSPs (SMSP = wid%4). __launch_bounds__(128,3) -> 3 blocks/SM ->
// 3 warps/SMSP on the whole chip (R3's proven depth, 2x the silicon).
// Step = R3 recipe: 4-acc f32x2 dot, renorm-by-p[0] every 4, exp-at-use,
// dist-4 raw emission prefetch. Fused last-block reduction.

#define Bn   1024
#define Tn   512
#define Cn   53
#define BOSi 1
#define EOSi 2
#define NCH  4
#define BURN 10

__device__ float    g_chunk[Bn * NCH];
__device__ unsigned g_ticket;   // zero-init; reset by last block each launch

typedef unsigned long long ull;

__device__ __forceinline__ ull pack2(float a, float b) {
    ull r; asm("mov.b64 %0, {%1,%2};" : "=l"(r) : "f"(a), "f"(b)); return r;
}
__device__ __forceinline__ void unpack2(ull v, float& a, float& b) {
    asm("mov.b64 {%0,%1}, %2;" : "=f"(a), "=f"(b) : "l"(v));
}
__device__ __forceinline__ void fma2(ull& acc, ull a, ull b) {
    asm("fma.rn.f32x2 %0, %1, %2, %0;" : "+l"(acc) : "l"(a), "l"(b));
}
__device__ __forceinline__ ull add2(ull a, ull b) {
    ull r; asm("add.rn.f32x2 %0, %1, %2;" : "=l"(r) : "l"(a), "l"(b)); return r;
}
__device__ __forceinline__ void lds_v2u64(unsigned addr, ull& x, ull& y) {
    asm volatile("ld.shared.v2.u64 {%0,%1}, [%2];" : "=l"(x), "=l"(y) : "r"(addr));
}

// one forward step (R3 recipe): dot, optional renorm by p[0], *exp(em), store
#define CRF_STEP(E0, E1, REN) do {                                          \
    unsigned pa_ = pbase + (unsigned)buf * 256u;                            \
    ull aA0_=0, aA1_=0, aB0_=0, aB1_=0;                                     \
    _Pragma("unroll")                                                       \
    for (int k_ = 0; k_ < 14; k_++) {                                       \
        ull x_, y_;                                                         \
        lds_v2u64(pa_ + 16u * k_, x_, y_);                                  \
        fma2(aA0_, x_, eA[2*k_]);  fma2(aA1_, y_, eA[2*k_+1]);              \
        fma2(aB0_, x_, eB[2*k_]);  fma2(aB1_, y_, eB[2*k_+1]);              \
    }                                                                       \
    float u_, v_, sA_, sB_;                                                 \
    unpack2(add2(aA0_, aA1_), u_, v_); sA_ = u_ + v_;                       \
    unpack2(add2(aB0_, aB1_), u_, v_); sB_ = u_ + v_;                       \
    float r_ = 1.0f;                                                        \
    if (REN) {                                                              \
        float s_ = prow[buf * 64];                                          \
        r_ = __fdividef(1.0f, s_);                                          \
        L += __logf(s_);                                                    \
    }                                                                       \
    float n0_ = sA_ * r_ * __expf(E0);                                      \
    float n1_ = sB_ * r_ * __expf(E1);                                      \
    buf ^= 1;                                                               \
    *(float2*)(prow + buf * 64 + 2 * lane) = make_float2(n0_, n1_);         \
    __syncwarp();                                                           \
    p0 = n0_; p1 = n1_;                                                     \
} while (0)

// burst-load 4 steps of RAW emissions (clamped row; exp applied at use)
#define LOAD4(P0A, P1A, BASEROW) do {                                       \
    _Pragma("unroll")                                                       \
    for (int j_ = 0; j_ < 4; j_++) {                                        \
        int rr_ = (BASEROW) + j_; if (rr_ > Tn - 1) rr_ = Tn - 1;           \
        const float* rp_ = emb + (size_t)rr_ * Cn;                          \
        P0A[j_] = __ldg(rp_ + c0v);                                         \
        P1A[j_] = __ldg(rp_ + c1v);                                         \
    }                                                                       \
} while (0)

// run the recurrence for t in [T0, T1) with dist-4 double-buffered prefetch
#define RUN_RANGE(T0, T1) do {                                              \
    int base_ = (T0);                                                       \
    LOAD4(xa, xb, base_);                                                   \
    for (;;) {                                                              \
        if (base_ + 4 > (T1)) break;                                        \
        LOAD4(ya, yb, base_ + 4);                                           \
        CRF_STEP(xa[0], xb[0], ((base_ + 0) & 3) == 2);                     \
        CRF_STEP(xa[1], xb[1], ((base_ + 1) & 3) == 2);                     \
        CRF_STEP(xa[2], xb[2], ((base_ + 2) & 3) == 2);                     \
        CRF_STEP(xa[3], xb[3], ((base_ + 3) & 3) == 2);                     \
        base_ += 4;                                                         \
        if (base_ + 4 > (T1)) break;                                        \
        LOAD4(xa, xb, base_ + 4);                                           \
        CRF_STEP(ya[0], yb[0], ((base_ + 0) & 3) == 2);                     \
        CRF_STEP(ya[1], yb[1], ((base_ + 1) & 3) == 2);                     \
        CRF_STEP(ya[2], yb[2], ((base_ + 2) & 3) == 2);                     \
        CRF_STEP(ya[3], yb[3], ((base_ + 3) & 3) == 2);                     \
        base_ += 4;                                                         \
    }                                                                       \
    for (int t_ = base_; t_ < (T1); t_++) {                                 \
        float e0_ = __ldg(emb + (size_t)t_ * Cn + c0v);                     \
        float e1_ = __ldg(emb + (size_t)t_ * Cn + c1v);                     \
        CRF_STEP(e0_, e1_, (t_ & 3) == 2);                                  \
    }                                                                       \
} while (0)

__global__ void __launch_bounds__(128, 3)
crf_fwd_kernel(const float* __restrict__ em,
               const int*   __restrict__ tags,
               const float* __restrict__ mask,
               const float* __restrict__ trans,
               float* __restrict__ out)
{
    __shared__ float trs[Cn * Cn];
    __shared__ __align__(16) float p_sm[4][2][64];  // [warp][buf][slot]
    __shared__ float rsum[4];
    __shared__ int   slast;

    const int tid  = threadIdx.x;
    const int lane = tid & 31;
    const int w    = tid >> 5;      // warp = chunk 0..3 (covers SMSP 0..3)
    const int b    = blockIdx.x;    // batch
    const int ch   = w;

    for (int i = tid; i < Cn * Cn; i += 128) trs[i] = trans[i];
    __syncthreads();

    const int  c0  = 2 * lane,            c1  = 2 * lane + 1;
    const bool okA = (c0 < Cn);           const bool okB = (c1 < Cn);
    const int  c0v = okA ? c0 : (Cn - 1); const int  c1v = okB ? c1 : (Cn - 1);

    const float* emb = em + (size_t)b * Tn * Cn;
    const int*   tg  = tags + b * Tn;
    float* prow = &p_sm[w][0][0];
    const unsigned pbase = (unsigned)__cvta_generic_to_shared(prow);

    // ---- sequence length = sum(mask) ----
    float ms = 0.f;
    for (int i = lane; i < Tn; i += 32) ms += mask[b * Tn + i];
#pragma unroll
    for (int off = 16; off; off >>= 1) ms += __shfl_xor_sync(~0u, ms, off);
    const int tl = (int)ms;   // steps run for t in [2, tl)

    // ---- chunk boundaries within [2, tl) ----
    const int s  = 2 + ((tl - 2) * ch) / NCH;
    const int e  = 2 + ((tl - 2) * (ch + 1)) / NCH;
    const int bs = (ch == 0) ? s : (s - BURN);   // s >= 2+63 for ch>0

    // ---- packed exp(transition) columns for this lane's 2 output cols ----
    ull eA[28], eB[28];
#pragma unroll
    for (int k = 0; k < 28; k++) {
        int r0 = 2 * k, r1 = 2 * k + 1;
        float a0 = (okA && r0 < Cn) ? __expf(trs[r0 * Cn + c0]) : 0.f;
        float a1 = (okA && r1 < Cn) ? __expf(trs[r1 * Cn + c0]) : 0.f;
        float b0 = (okB && r0 < Cn) ? __expf(trs[r0 * Cn + c1]) : 0.f;
        float b1 = (okB && r1 < Cn) ? __expf(trs[r1 * Cn + c1]) : 0.f;
        eA[k] = pack2(a0, a1);
        eB[k] = pack2(b0, b1);
    }

    // ---- init ----
    float p0, p1;
    if (ch == 0) {   // exact alpha_1 in prob domain
        p0 = okA ? __expf(trs[BOSi * Cn + c0] + emb[Cn + c0]) : 0.f;
        p1 = okB ? __expf(trs[BOSi * Cn + c1] + emb[Cn + c1]) : 0.f;
    } else {         // uniform (burn-in contracts it to ~1e-9 direction err)
        p0 = okA ? 1.0f : 0.f;
        p1 = okB ? 1.0f : 0.f;
    }
    int buf = 0;
    *(float2*)(prow + 2 * lane) = make_float2(p0, p1);
    __syncwarp();

    float L = 0.f;
    float xa[4], xb[4], ya[4], yb[4];

    // ---- burn-in (ch>0) then boundary snapshot ----
    float Lb = 0.f, logBeta = 0.f;
    if (ch != 0) {
        RUN_RANGE(bs, s);
        Lb = L;
        float beta = p0 + p1;
#pragma unroll
        for (int off = 16; off; off >>= 1) beta += __shfl_xor_sync(~0u, beta, off);
        logBeta = __logf(beta);
    }

    // ---- owned segment ----
    RUN_RANGE(s, e);

    // ---- chunk contribution ----
    float endv;
    if (ch == NCH - 1) {
        endv = p0 * __expf(trs[c0v * Cn + EOSi]) + p1 * __expf(trs[c1v * Cn + EOSi]);
    } else {
        endv = p0 + p1;
    }
#pragma unroll
    for (int off = 16; off; off >>= 1) endv += __shfl_xor_sync(~0u, endv, off);
    float contrib = L - Lb - logBeta + __logf(endv);

    // ---- gold-path score slice for [s, e) ----
    float sc = 0.f;
    for (int t = s + lane; t < e; t += 32) {
        int a = tg[t - 1], c = tg[t];
        sc += emb[(size_t)t * Cn + c] + trs[a * Cn + c];
    }
#pragma unroll
    for (int off = 16; off; off >>= 1) sc += __shfl_xor_sync(~0u, sc, off);

    if (lane == 0) {
        if (ch == 0) {
            int t1 = tg[1];
            sc += trs[BOSi * Cn + t1] + emb[Cn + t1];
        }
        if (ch == NCH - 1) {
            int lt = tg[tl];   // tags at index == length
            sc += trs[lt * Cn + EOSi];
        }
        g_chunk[(b << 2) | ch] = contrib - sc;
    }

    // ---- fused reduction: last block sums all chunk contributions ----
    __threadfence();
    __syncthreads();
    if (tid == 0) {
        unsigned tk = atomicAdd(&g_ticket, 1u);
        slast = (tk == (unsigned)(gridDim.x - 1)) ? 1 : 0;
    }
    __syncthreads();
    if (slast) {
        __threadfence();
        float acc = 0.f;
        for (int i = tid; i < Bn * NCH; i += 128) acc += __ldcg(&g_chunk[i]);
#pragma unroll
        for (int off = 16; off; off >>= 1) acc += __shfl_xor_sync(~0u, acc, off);
        if (lane == 0) rsum[w] = acc;
        __syncthreads();
        if (tid == 0) {
            out[0] = rsum[0] + rsum[1] + rsum[2] + rsum[3];
            g_ticket = 0;   // reset for next graph replay
        }
    }
}

extern "C" void kernel_launch(void* const* d_in, const int* in_sizes, int n_in,
                              void* d_out, int out_size)
{
    const float* em    = (const float*)d_in[0];
    const int*   tags  = (const int*)  d_in[1];
    const float* mask  = (const float*)d_in[2];
    const float* trans = (const float*)d_in[3];
    float* out = (float*)d_out;

    crf_fwd_kernel<<<Bn, 128>>>(em, tags, mask, trans, out);
}

// round 13
// speedup vs baseline: 2.4784x; 1.5788x over previous
#include <cuda_runtime.h>
#include <cuda_bf16.h>

#define Bn 1024
#define Tn 512
#define Cn 53
#define BOSi 1
#define EOSi 2

__device__ float g_chunk[Bn*16];
__device__ float g_score[Bn];
__device__ unsigned g_ticket;

__device__ __forceinline__ unsigned cvt2(float lo, float hi){
    unsigned r; asm("cvt.rn.bf16x2.f32 %0, %1, %2;" : "=r"(r) : "f"(hi), "f"(lo)); return r;
}
__device__ __forceinline__ void mma_acc(float* d, const unsigned* a, unsigned b0, unsigned b1){
    asm("mma.sync.aligned.m16n8k16.row.col.f32.bf16.bf16.f32 "
        "{%0,%1,%2,%3},{%4,%5,%6,%7},{%8,%9},{%0,%1,%2,%3};"
        : "+f"(d[0]),"+f"(d[1]),"+f"(d[2]),"+f"(d[3])
        : "r"(a[0]),"r"(a[1]),"r"(a[2]),"r"(a[3]),"r"(b0),"r"(b1));
}

__global__ void __launch_bounds__(128)
crf_mma_kernel(const float* __restrict__ em, const int* __restrict__ tags,
               const float* __restrict__ mask, const float* __restrict__ trans,
               float* __restrict__ out)
{
    __shared__ float trs[Cn*Cn];
    __shared__ uint2 EF[4][8][32];   // B-fragments of E (bf16), padded 64x64
    __shared__ float eos_sm[64];
    __shared__ float rr[4];
    __shared__ int slast;

    const int tid = threadIdx.x, lane = tid&31, w = tid>>5;
    const int q = lane&3, g = lane>>2;

    for (int i=tid;i<Cn*Cn;i+=128) trs[i]=trans[i];
    __syncthreads();
    if (tid<64) eos_sm[tid] = (tid<Cn)? __expf(trs[tid*Cn+EOSi]) : 0.f;
    if (tid<32){
        for (int kt=0;kt<4;kt++) for (int nt=0;nt<8;nt++){
            int n = 8*nt + (tid>>2);
            int k0 = 16*kt + 2*(tid&3);
            float e00=0,e01=0,e10=0,e11=0;
            if (n<Cn){
                if (k0  <Cn) e00=__expf(trs[(k0  )*Cn+n]);
                if (k0+1<Cn) e01=__expf(trs[(k0+1)*Cn+n]);
                if (k0+8<Cn) e10=__expf(trs[(k0+8)*Cn+n]);
                if (k0+9<Cn) e11=__expf(trs[(k0+9)*Cn+n]);
            }
            EF[kt][nt][tid] = make_uint2(cvt2(e00,e01), cvt2(e10,e11));
        }
    }
    __syncthreads();

    const int gw = blockIdx.x*4 + w;   // warp -> 2 batches, 16 chunks each
    const int bA = gw*2;
    const float* embA = em + (size_t)bA*Tn*Cn;
    const float* embB = embA + (size_t)Tn*Cn;
    const float* emP[2] = {embA, embB};

    float msA=0, msB=0;
    for (int i=lane;i<Tn;i+=32){ msA+=mask[bA*Tn+i]; msB+=mask[(bA+1)*Tn+i]; }
    for (int o=16;o;o>>=1){ msA+=__shfl_xor_sync(~0u,msA,o); msB+=__shfl_xor_sync(~0u,msB,o); }
    const int tlA=(int)msA, tlB=(int)msB;

    // rows: idx0=row g (A,ch g), idx1=row g+8 (A,ch g+8), idx2/3 same for B
    int bs[4], iS[4], iE[4];
    float L[4]={0,0,0,0}, Ls[4]={0,0,0,0}, Le[4]={0,0,0,0}, sc[4]={1,1,1,1};
    int imax=0;
    #pragma unroll
    for (int idx=0;idx<4;idx++){
        int mt=idx>>1, ch=g+8*(idx&1);
        int len = (mt? tlB:tlA) - 2;
        int s = 2 + (len*ch)/16;
        int e = 2 + (len*(ch+1))/16;
        bs[idx] = (ch==0)? 2 : s-8;          // BURN=8
        iS[idx] = (ch==0)? -1 : 7;           // boundary after burn-in
        iE[idx] = e-1-bs[idx];
        if (iE[idx]+1>imax) imax=iE[idx]+1;
    }
    for (int o=16;o;o>>=1){ int v=__shfl_xor_sync(~0u,imax,o); if(v>imax) imax=v; }

    // init P: chunk0 rows = exact alpha_1 (prob domain), others uniform 1
    float P[2][8][4];
    #pragma unroll
    for (int mt=0;mt<2;mt++)
    #pragma unroll
    for (int nt=0;nt<8;nt++)
    #pragma unroll
    for (int r=0;r<4;r++){
        int h=r>>1, d=r&1;
        int j = 8*nt + 2*q + d;
        int ch = g + 8*h;
        float v;
        if (j>=Cn) v=0.f;
        else if (ch==0) v=__expf(trs[BOSi*Cn+j] + __ldg(emP[mt]+Cn+j));
        else v=1.f;
        P[mt][nt][r]=v;
    }

    for (int i0=0;i0<imax;i0+=4){
      #pragma unroll
      for (int ii=0;ii<4;ii++){
        const int i = i0+ii;
        float ev[4][14];
        #pragma unroll
        for (int idx=0;idx<4;idx++){
            int t = bs[idx]+i; if (t>510) t=510;
            const float* rp = emP[idx>>1] + (size_t)t*Cn;
            #pragma unroll
            for (int nt=0;nt<7;nt++){
                int c0 = 8*nt+2*q; int c1 = c0+1;
                if (c0>52) c0=52; if (c1>52) c1=52;
                ev[idx][2*nt]  =__ldg(rp+c0);
                ev[idx][2*nt+1]=__ldg(rp+c1);
            }
        }
        // P = (sc .* P) @ E  via m16n8k16 bf16 MMA; C-frag chains into A-frag
        #pragma unroll
        for (int mt=0;mt<2;mt++){
            unsigned Af[4][4];
            #pragma unroll
            for (int kt=0;kt<4;kt++){
                Af[kt][0]=cvt2(sc[2*mt]*P[mt][2*kt][0],    sc[2*mt]*P[mt][2*kt][1]);
                Af[kt][1]=cvt2(sc[2*mt+1]*P[mt][2*kt][2],  sc[2*mt+1]*P[mt][2*kt][3]);
                Af[kt][2]=cvt2(sc[2*mt]*P[mt][2*kt+1][0],  sc[2*mt]*P[mt][2*kt+1][1]);
                Af[kt][3]=cvt2(sc[2*mt+1]*P[mt][2*kt+1][2],sc[2*mt+1]*P[mt][2*kt+1][3]);
            }
            #pragma unroll
            for (int nt=0;nt<8;nt++){
                P[mt][nt][0]=0.f;P[mt][nt][1]=0.f;P[mt][nt][2]=0.f;P[mt][nt][3]=0.f;
                #pragma unroll
                for (int kt=0;kt<4;kt++){
                    uint2 bb = EF[kt][nt][lane];
                    mma_acc(P[mt][nt], Af[kt], bb.x, bb.y);
                }
            }
        }
        // emission exp + multiply (pad cols stay 0)
        #pragma unroll
        for (int idx=0;idx<4;idx++)
        #pragma unroll
        for (int k=0;k<14;k++) ev[idx][k]=__expf(ev[idx][k]);
        #pragma unroll
        for (int mt=0;mt<2;mt++)
        #pragma unroll
        for (int nt=0;nt<7;nt++){
            P[mt][nt][0]*=ev[2*mt][2*nt];   P[mt][nt][1]*=ev[2*mt][2*nt+1];
            P[mt][nt][2]*=ev[2*mt+1][2*nt]; P[mt][nt][3]*=ev[2*mt+1][2*nt+1];
        }
        // row sums (per chain) + EOS dots for rows g+8
        float rs[4], ed[2];
        #pragma unroll
        for (int idx=0;idx<4;idx++){
            int mt=idx>>1, h=idx&1;
            float s=0;
            #pragma unroll
            for (int nt=0;nt<7;nt++) s += P[mt][nt][2*h]+P[mt][nt][2*h+1];
            s += __shfl_xor_sync(~0u,s,1); s += __shfl_xor_sync(~0u,s,2);
            rs[idx]=s;
        }
        #pragma unroll
        for (int mt=0;mt<2;mt++){
            float s=0;
            #pragma unroll
            for (int nt=0;nt<7;nt++)
                s += P[mt][nt][2]*eos_sm[8*nt+2*q] + P[mt][nt][3]*eos_sm[8*nt+2*q+1];
            s += __shfl_xor_sync(~0u,s,1); s += __shfl_xor_sync(~0u,s,2);
            ed[mt]=s;
        }
        // predicated bookkeeping (uniform control flow)
        #pragma unroll
        for (int idx=0;idx<4;idx++){
            float lrs = __logf(rs[idx]);
            bool last = ((idx&1)==1) && (g==7);    // chunk 15
            float lev = last ? __logf(ed[idx>>1]) : lrs;
            if (i==iS[idx]) Ls[idx]=L[idx]+lrs;
            if (i==iE[idx]) Le[idx]=L[idx]+lev;
            if (ii==3){ L[idx]+=lrs; sc[idx]=__fdividef(1.f,rs[idx]); }
            else sc[idx]=1.f;
        }
      }
    }

    // gold-path scores: half-warp per batch
    {
        int half = lane>>4;
        const float* embS = emP[half];
        const int* tgS = tags + (bA+half)*Tn;
        int tlS = half? tlB: tlA;
        float scv=0;
        for (int t=2+(lane&15); t<tlS; t+=16){
            int a=tgS[t-1], c=tgS[t];
            scv += embS[(size_t)t*Cn+c] + trs[a*Cn+c];
        }
        for (int o=8;o;o>>=1) scv += __shfl_xor_sync(~0u,scv,o);
        if ((lane&15)==0){
            int t1=tgS[1];
            float first = trs[BOSi*Cn+t1] + embS[Cn+t1];
            int lt=tgS[tlS];
            g_score[bA+half] = first + scv + trs[lt*Cn+EOSi];
        }
    }
    if (q==0){
        #pragma unroll
        for (int idx=0;idx<4;idx++){
            int mt=idx>>1, ch=g+8*(idx&1);
            g_chunk[(bA+mt)*16+ch] = Le[idx]-Ls[idx];
        }
    }

    // fused last-block reduction
    __threadfence();
    __syncthreads();
    if (tid==0) slast = (atomicAdd(&g_ticket,1u)==(unsigned)(gridDim.x-1)) ? 1 : 0;
    __syncthreads();
    if (slast){
        __threadfence();
        float acc=0;
        for (int i=tid;i<Bn*16;i+=128) acc += __ldcg(&g_chunk[i]);
        for (int i=tid;i<Bn;i+=128)    acc -= __ldcg(&g_score[i]);
        for (int o=16;o;o>>=1) acc += __shfl_xor_sync(~0u,acc,o);
        if (lane==0) rr[w]=acc;
        __syncthreads();
        if (tid==0){ out[0]=rr[0]+rr[1]+rr[2]+rr[3]; g_ticket=0; }
    }
}

extern "C" void kernel_launch(void* const* d_in, const int* in_sizes, int n_in,
                              void* d_out, int out_size)
{
    const float* em    = (const float*)d_in[0];
    const int*   tags  = (const int*)  d_in[1];
    const float* mask  = (const float*)d_in[2];
    const float* trans = (const float*)d_in[3];
    float* out = (float*)d_out;

    crf_mma_kernel<<<Bn/8, 128>>>(em, tags, mask, trans, out);
}

// round 14
// speedup vs baseline: 2.7445x; 1.1074x over previous
#include <cuda_runtime.h>
#include <cuda_bf16.h>

#define Bn 1024
#define Tn 512
#define Cn 53
#define BOSi 1
#define EOSi 2
#define NCH 32

__device__ float g_chunk[Bn*NCH];
__device__ float g_score[Bn];
__device__ unsigned g_ticket;

__device__ __forceinline__ unsigned cvt2(float lo, float hi){
    unsigned r; asm("cvt.rn.bf16x2.f32 %0, %1, %2;" : "=r"(r) : "f"(hi), "f"(lo)); return r;
}
__device__ __forceinline__ void mma_acc(float* d, const unsigned* a, unsigned b0, unsigned b1){
    asm("mma.sync.aligned.m16n8k16.row.col.f32.bf16.bf16.f32 "
        "{%0,%1,%2,%3},{%4,%5,%6,%7},{%8,%9},{%0,%1,%2,%3};"
        : "+f"(d[0]),"+f"(d[1]),"+f"(d[2]),"+f"(d[3])
        : "r"(a[0]),"r"(a[1]),"r"(a[2]),"r"(a[3]),"r"(b0),"r"(b1));
}

__global__ void __launch_bounds__(128)
crf_mma_kernel(const float* __restrict__ em, const int* __restrict__ tags,
               const float* __restrict__ mask, const float* __restrict__ trans,
               float* __restrict__ out)
{
    __shared__ float trs[Cn*Cn];
    __shared__ uint2 EF[4][8][32];   // bf16 B-fragments of E=exp(T), padded 64x64
    __shared__ float eos_sm[64];
    __shared__ float rr[4];
    __shared__ int slast;

    const int tid = threadIdx.x, lane = tid&31, w = tid>>5;
    const int q = lane&3, g = lane>>2;

    for (int i=tid;i<Cn*Cn;i+=128) trs[i]=trans[i];
    __syncthreads();
    if (tid<64) eos_sm[tid] = (tid<Cn)? __expf(trs[tid*Cn+EOSi]) : 0.f;
    if (tid<32){
        for (int kt=0;kt<4;kt++) for (int nt=0;nt<8;nt++){
            int n = 8*nt + (tid>>2);
            int k0 = 16*kt + 2*(tid&3);
            float e00=0,e01=0,e10=0,e11=0;
            if (n<Cn){
                if (k0  <Cn) e00=__expf(trs[(k0  )*Cn+n]);
                if (k0+1<Cn) e01=__expf(trs[(k0+1)*Cn+n]);
                if (k0+8<Cn) e10=__expf(trs[(k0+8)*Cn+n]);
                if (k0+9<Cn) e11=__expf(trs[(k0+9)*Cn+n]);
            }
            EF[kt][nt][tid] = make_uint2(cvt2(e00,e01), cvt2(e10,e11));
        }
    }
    __syncthreads();

    // warp -> ONE batch, 32 chunks. row = g + 8*h + 16*mt = chunk id.
    const int b = blockIdx.x*4 + w;
    const float* emb = em + (size_t)b*Tn*Cn;
    const int* tg = tags + b*Tn;

    float ms=0;
    for (int i=lane;i<Tn;i+=32) ms += mask[b*Tn+i];
    for (int o=16;o;o>>=1) ms += __shfl_xor_sync(~0u,ms,o);
    const int tl=(int)ms;
    const int len = tl-2;

    int bs[4], iS[4], iE[4];
    float L[4]={0,0,0,0}, contrib[4]={0,0,0,0}, sc[4]={1,1,1,1};
    int imax=0;
    #pragma unroll
    for (int idx=0;idx<4;idx++){
        int ch = g + 8*(idx&1) + 16*(idx>>1);
        int s = 2 + (len*ch)/NCH;
        int e = 2 + (len*(ch+1))/NCH;
        bs[idx] = (ch==0)? 2 : s-8;          // BURN=8
        iS[idx] = (ch==0)? -1 : 7;           // boundary snapshot step
        iE[idx] = e-1-bs[idx];
        if (iE[idx]+1>imax) imax=iE[idx]+1;
    }
    for (int o=16;o;o>>=1){ int v=__shfl_xor_sync(~0u,imax,o); if(v>imax) imax=v; }

    // init P: chunk0 = exact alpha_1 (prob domain), others uniform 1
    float P[2][8][4];
    #pragma unroll
    for (int mt=0;mt<2;mt++)
    #pragma unroll
    for (int nt=0;nt<8;nt++)
    #pragma unroll
    for (int r=0;r<4;r++){
        int h=r>>1, d=r&1;
        int j = 8*nt + 2*q + d;
        int ch = g + 8*h + 16*mt;
        float v;
        if (j>=Cn) v=0.f;
        else if (ch==0) v=__expf(trs[BOSi*Cn+j] + __ldg(emb+Cn+j));
        else v=1.f;
        P[mt][nt][r]=v;
    }

    for (int i0=0;i0<imax;i0+=4){
      #pragma unroll
      for (int ii=0;ii<4;ii++){
        const int i = i0+ii;
        // load raw emissions for the 4 rows this thread owns
        float ev[4][14];
        #pragma unroll
        for (int idx=0;idx<4;idx++){
            int t = bs[idx]+i; if (t>510) t=510;
            const float* rp = emb + (size_t)t*Cn;
            #pragma unroll
            for (int nt=0;nt<7;nt++){
                int c0 = 8*nt+2*q; int c1 = c0+1;
                if (c0>52) c0=52; if (c1>52) c1=52;
                ev[idx][2*nt]  =__ldg(rp+c0);
                ev[idx][2*nt+1]=__ldg(rp+c1);
            }
        }
        // P = (sc .* P) @ E : C-fragment chains directly into A-fragment
        #pragma unroll
        for (int mt=0;mt<2;mt++){
            unsigned Af[4][4];
            #pragma unroll
            for (int kt=0;kt<4;kt++){
                Af[kt][0]=cvt2(sc[2*mt]*P[mt][2*kt][0],    sc[2*mt]*P[mt][2*kt][1]);
                Af[kt][1]=cvt2(sc[2*mt+1]*P[mt][2*kt][2],  sc[2*mt+1]*P[mt][2*kt][3]);
                Af[kt][2]=cvt2(sc[2*mt]*P[mt][2*kt+1][0],  sc[2*mt]*P[mt][2*kt+1][1]);
                Af[kt][3]=cvt2(sc[2*mt+1]*P[mt][2*kt+1][2],sc[2*mt+1]*P[mt][2*kt+1][3]);
            }
            #pragma unroll
            for (int nt=0;nt<8;nt++){
                P[mt][nt][0]=0.f;P[mt][nt][1]=0.f;P[mt][nt][2]=0.f;P[mt][nt][3]=0.f;
                #pragma unroll
                for (int kt=0;kt<4;kt++){
                    uint2 bb = EF[kt][nt][lane];
                    mma_acc(P[mt][nt], Af[kt], bb.x, bb.y);
                }
            }
        }
        // emission exp + multiply (pad cols stay 0)
        #pragma unroll
        for (int idx=0;idx<4;idx++)
        #pragma unroll
        for (int k=0;k<14;k++) ev[idx][k]=__expf(ev[idx][k]);
        #pragma unroll
        for (int mt=0;mt<2;mt++)
        #pragma unroll
        for (int nt=0;nt<7;nt++){
            P[mt][nt][0]*=ev[2*mt][2*nt];   P[mt][nt][1]*=ev[2*mt][2*nt+1];
            P[mt][nt][2]*=ev[2*mt+1][2*nt]; P[mt][nt][3]*=ev[2*mt+1][2*nt+1];
        }
        // per-chain row sums (quad reduction) + EOS dot (row 31 lives in mt=1,h=1)
        float rs[4];
        #pragma unroll
        for (int idx=0;idx<4;idx++){
            int mt=idx>>1, h=idx&1;
            float s=0;
            #pragma unroll
            for (int nt=0;nt<7;nt++) s += P[mt][nt][2*h]+P[mt][nt][2*h+1];
            s += __shfl_xor_sync(~0u,s,1); s += __shfl_xor_sync(~0u,s,2);
            rs[idx]=s;
        }
        float ed;
        {
            float s=0;
            #pragma unroll
            for (int nt=0;nt<7;nt++)
                s += P[1][nt][2]*eos_sm[8*nt+2*q] + P[1][nt][3]*eos_sm[8*nt+2*q+1];
            s += __shfl_xor_sync(~0u,s,1); s += __shfl_xor_sync(~0u,s,2);
            ed=s;
        }
        // predicated bookkeeping (uniform control flow within quads)
        #pragma unroll
        for (int idx=0;idx<4;idx++){
            float lrs = __logf(rs[idx]);
            bool last = (idx==3) && (g==7);            // chunk 31
            float lev = last ? __logf(ed) : lrs;
            if (i==iS[idx]) contrib[idx] -= L[idx]+lrs;
            if (i==iE[idx]) contrib[idx] += L[idx]+lev;
            if (ii==3){ L[idx]+=lrs; sc[idx]=__fdividef(1.f,rs[idx]); }
            else sc[idx]=1.f;
        }
      }
    }

    // gold-path score: whole warp on this batch
    {
        float scv=0;
        for (int t=2+lane; t<tl; t+=32){
            int a=tg[t-1], c=tg[t];
            scv += emb[(size_t)t*Cn+c] + trs[a*Cn+c];
        }
        for (int o=16;o;o>>=1) scv += __shfl_xor_sync(~0u,scv,o);
        if (lane==0){
            int t1=tg[1];
            float first = trs[BOSi*Cn+t1] + emb[Cn+t1];
            int lt=tg[tl];
            g_score[b] = first + scv + trs[lt*Cn+EOSi];
        }
    }
    if (q==0){
        #pragma unroll
        for (int idx=0;idx<4;idx++){
            int ch = g + 8*(idx&1) + 16*(idx>>1);
            g_chunk[b*NCH+ch] = contrib[idx];
        }
    }

    // fused last-block reduction
    __threadfence();
    __syncthreads();
    if (tid==0) slast = (atomicAdd(&g_ticket,1u)==(unsigned)(gridDim.x-1)) ? 1 : 0;
    __syncthreads();
    if (slast){
        __threadfence();
        float acc=0;
        for (int i=tid;i<Bn*NCH;i+=128) acc += __ldcg(&g_chunk[i]);
        for (int i=tid;i<Bn;i+=128)     acc -= __ldcg(&g_score[i]);
        for (int o=16;o;o>>=1) acc += __shfl_xor_sync(~0u,acc,o);
        if (lane==0) rr[w]=acc;
        __syncthreads();
        if (tid==0){ out[0]=rr[0]+rr[1]+rr[2]+rr[3]; g_ticket=0; }
    }
}

extern "C" void kernel_launch(void* const* d_in, const int* in_sizes, int n_in,
                              void* d_out, int out_size)
{
    const float* em    = (const float*)d_in[0];
    const int*   tags  = (const int*)  d_in[1];
    const float* mask  = (const float*)d_in[2];
    const float* trans = (const float*)d_in[3];
    float* out = (float*)d_out;

    crf_mma_kernel<<<Bn/4, 128>>>(em, tags, mask, trans, out);
}

// round 15
// speedup vs baseline: 2.7457x; 1.0004x over previous
#include <cuda_runtime.h>
#include <cuda_bf16.h>

#define Bn 1024
#define Tn 512
#define Cn 53
#define BOSi 1
#define EOSi 2
#define NCH 32

__device__ float g_chunk[Bn*NCH];
__device__ float g_score[Bn];
__device__ unsigned g_ticket;

__device__ __forceinline__ unsigned cvt2(float lo, float hi){
    unsigned r; asm("cvt.rn.bf16x2.f32 %0, %1, %2;" : "=r"(r) : "f"(hi), "f"(lo)); return r;
}
__device__ __forceinline__ void mma_acc(float* d, const unsigned* a, unsigned b0, unsigned b1){
    asm("mma.sync.aligned.m16n8k16.row.col.f32.bf16.bf16.f32 "
        "{%0,%1,%2,%3},{%4,%5,%6,%7},{%8,%9},{%0,%1,%2,%3};"
        : "+f"(d[0]),"+f"(d[1]),"+f"(d[2]),"+f"(d[3])
        : "r"(a[0]),"r"(a[1]),"r"(a[2]),"r"(a[3]),"r"(b0),"r"(b1));
}

__global__ void __launch_bounds__(128, 3)
crf_mma_kernel(const float* __restrict__ em, const int* __restrict__ tags,
               const float* __restrict__ mask, const float* __restrict__ trans,
               float* __restrict__ out)
{
    __shared__ float trs[Cn*Cn];
    __shared__ uint2 EF[4][7][32];   // bf16 B-fragments of E=exp(T), 64x56 (N=56)
    __shared__ float eos_sm[64];
    __shared__ float rr[4];
    __shared__ int slast;

    const int tid = threadIdx.x, lane = tid&31, w = tid>>5;
    const int q = lane&3, g = lane>>2;

    for (int i=tid;i<Cn*Cn;i+=128) trs[i]=trans[i];
    __syncthreads();
    if (tid<64) eos_sm[tid] = (tid<Cn)? __expf(trs[tid*Cn+EOSi]) : 0.f;
    if (tid<32){
        for (int kt=0;kt<4;kt++) for (int nt=0;nt<7;nt++){
            int n = 8*nt + (tid>>2);
            int k0 = 16*kt + 2*(tid&3);
            float e00=0,e01=0,e10=0,e11=0;
            if (n<Cn){
                if (k0  <Cn) e00=__expf(trs[(k0  )*Cn+n]);
                if (k0+1<Cn) e01=__expf(trs[(k0+1)*Cn+n]);
                if (k0+8<Cn) e10=__expf(trs[(k0+8)*Cn+n]);
                if (k0+9<Cn) e11=__expf(trs[(k0+9)*Cn+n]);
            }
            EF[kt][nt][tid] = make_uint2(cvt2(e00,e01), cvt2(e10,e11));
        }
    }
    __syncthreads();

    // warp -> ONE batch, 32 chunks. row = g + 8*h + 16*mt = chunk id.
    const int b = blockIdx.x*4 + w;
    const float* emb = em + (size_t)b*Tn*Cn;
    const int* tg = tags + b*Tn;

    float ms=0;
    for (int i=lane;i<Tn;i+=32) ms += mask[b*Tn+i];
    for (int o=16;o;o>>=1) ms += __shfl_xor_sync(~0u,ms,o);
    const int tl=(int)ms;
    const int len = tl-2;

    int bs[4], iS[4], iE[4];
    float L[4]={0,0,0,0}, contrib[4]={0,0,0,0}, sc[4]={1,1,1,1};
    int imax=0;
    #pragma unroll
    for (int idx=0;idx<4;idx++){
        int ch = g + 8*(idx&1) + 16*(idx>>1);
        int s = 2 + (len*ch)/NCH;
        int e = 2 + (len*(ch+1))/NCH;
        bs[idx] = (ch==0)? 2 : s-8;          // BURN=8
        iS[idx] = (ch==0)? -1 : 7;
        iE[idx] = e-1-bs[idx];
        if (iE[idx]+1>imax) imax=iE[idx]+1;
    }
    for (int o=16;o;o>>=1){ int v=__shfl_xor_sync(~0u,imax,o); if(v>imax) imax=v; }

    // init P (N=56: nt<7): chunk0 = exact alpha_1 (prob), others uniform 1
    float P[2][7][4];
    #pragma unroll
    for (int mt=0;mt<2;mt++)
    #pragma unroll
    for (int nt=0;nt<7;nt++)
    #pragma unroll
    for (int r=0;r<4;r++){
        int h=r>>1, d=r&1;
        int j = 8*nt + 2*q + d;
        int ch = g + 8*h + 16*mt;
        float v;
        if (j>=Cn) v=0.f;
        else if (ch==0) v=__expf(trs[BOSi*Cn+j] + __ldg(emb+Cn+j));
        else v=1.f;
        P[mt][nt][r]=v;
    }

    for (int i0=0;i0<imax;i0+=4){
      #pragma unroll
      for (int ii=0;ii<4;ii++){
        const int i = i0+ii;
        float ev[4][14];
        #pragma unroll
        for (int idx=0;idx<4;idx++){
            int t = bs[idx]+i; if (t>510) t=510;
            const float* rp = emb + (size_t)t*Cn;
            #pragma unroll
            for (int nt=0;nt<7;nt++){
                int c0 = 8*nt+2*q; int c1 = c0+1;
                if (c0>52) c0=52; if (c1>52) c1=52;
                ev[idx][2*nt]  =__ldg(rp+c0);
                ev[idx][2*nt+1]=__ldg(rp+c1);
            }
        }
        // P = (sc .* P) @ E  (C-frag chains into A-frag; k-tile 3 upper half = 0)
        #pragma unroll
        for (int mt=0;mt<2;mt++){
            unsigned Af[4][4];
            #pragma unroll
            for (int kt=0;kt<3;kt++){
                Af[kt][0]=cvt2(sc[2*mt]*P[mt][2*kt][0],    sc[2*mt]*P[mt][2*kt][1]);
                Af[kt][1]=cvt2(sc[2*mt+1]*P[mt][2*kt][2],  sc[2*mt+1]*P[mt][2*kt][3]);
                Af[kt][2]=cvt2(sc[2*mt]*P[mt][2*kt+1][0],  sc[2*mt]*P[mt][2*kt+1][1]);
                Af[kt][3]=cvt2(sc[2*mt+1]*P[mt][2*kt+1][2],sc[2*mt+1]*P[mt][2*kt+1][3]);
            }
            Af[3][0]=cvt2(sc[2*mt]*P[mt][6][0],   sc[2*mt]*P[mt][6][1]);
            Af[3][1]=cvt2(sc[2*mt+1]*P[mt][6][2], sc[2*mt+1]*P[mt][6][3]);
            Af[3][2]=0u; Af[3][3]=0u;   // cols 56..63 are structurally zero
            #pragma unroll
            for (int nt=0;nt<7;nt++){
                P[mt][nt][0]=0.f;P[mt][nt][1]=0.f;P[mt][nt][2]=0.f;P[mt][nt][3]=0.f;
                #pragma unroll
                for (int kt=0;kt<4;kt++){
                    uint2 bb = EF[kt][nt][lane];
                    mma_acc(P[mt][nt], Af[kt], bb.x, bb.y);
                }
            }
        }
        // emission exp + multiply
        #pragma unroll
        for (int idx=0;idx<4;idx++)
        #pragma unroll
        for (int k=0;k<14;k++) ev[idx][k]=__expf(ev[idx][k]);
        #pragma unroll
        for (int mt=0;mt<2;mt++)
        #pragma unroll
        for (int nt=0;nt<7;nt++){
            P[mt][nt][0]*=ev[2*mt][2*nt];   P[mt][nt][1]*=ev[2*mt][2*nt+1];
            P[mt][nt][2]*=ev[2*mt+1][2*nt]; P[mt][nt][3]*=ev[2*mt+1][2*nt+1];
        }
        // per-chain row sums (quad reduction)
        float rs[4];
        #pragma unroll
        for (int idx=0;idx<4;idx++){
            int mt=idx>>1, h=idx&1;
            float s=0;
            #pragma unroll
            for (int nt=0;nt<7;nt++) s += P[mt][nt][2*h]+P[mt][nt][2*h+1];
            s += __shfl_xor_sync(~0u,s,1); s += __shfl_xor_sync(~0u,s,2);
            rs[idx]=s;
        }
        // bookkeeping; EOS dot only for chunk 31's quad at its end step
        #pragma unroll
        for (int idx=0;idx<4;idx++){
            float lrs = __logf(rs[idx]);
            float lev = lrs;
            if (idx==3){
                if (g==7 && i==iE[3]){
                    unsigned m = __activemask();
                    float s=0;
                    #pragma unroll
                    for (int nt=0;nt<7;nt++)
                        s += P[1][nt][2]*eos_sm[8*nt+2*q] + P[1][nt][3]*eos_sm[8*nt+2*q+1];
                    s += __shfl_xor_sync(m,s,1); s += __shfl_xor_sync(m,s,2);
                    lev = __logf(s);
                }
            }
            if (i==iS[idx]) contrib[idx] -= L[idx]+lrs;
            if (i==iE[idx]) contrib[idx] += L[idx]+lev;
            if (ii==3){ L[idx]+=lrs; sc[idx]=__fdividef(1.f,rs[idx]); }
            else sc[idx]=1.f;
        }
      }
    }

    // gold-path score: whole warp on this batch
    {
        float scv=0;
        for (int t=2+lane; t<tl; t+=32){
            int a=tg[t-1], c=tg[t];
            scv += emb[(size_t)t*Cn+c] + trs[a*Cn+c];
        }
        for (int o=16;o;o>>=1) scv += __shfl_xor_sync(~0u,scv,o);
        if (lane==0){
            int t1=tg[1];
            float first = trs[BOSi*Cn+t1] + emb[Cn+t1];
            int lt=tg[tl];
            g_score[b] = first + scv + trs[lt*Cn+EOSi];
        }
    }
    if (q==0){
        #pragma unroll
        for (int idx=0;idx<4;idx++){
            int ch = g + 8*(idx&1) + 16*(idx>>1);
            g_chunk[b*NCH+ch] = contrib[idx];
        }
    }

    // fused last-block reduction
    __threadfence();
    __syncthreads();
    if (tid==0) slast = (atomicAdd(&g_ticket,1u)==(unsigned)(gridDim.x-1)) ? 1 : 0;
    __syncthreads();
    if (slast){
        __threadfence();
        float acc=0;
        for (int i=tid;i<Bn*NCH;i+=128) acc += __ldcg(&g_chunk[i]);
        for (int i=tid;i<Bn;i+=128)     acc -= __ldcg(&g_score[i]);
        for (int o=16;o;o>>=1) acc += __shfl_xor_sync(~0u,acc,o);
        if (lane==0) rr[w]=acc;
        __syncthreads();
        if (tid==0){ out[0]=rr[0]+rr[1]+rr[2]+rr[3]; g_ticket=0; }
    }
}

extern "C" void kernel_launch(void* const* d_in, const int* in_sizes, int n_in,
                              void* d_out, int out_size)
{
    const float* em    = (const float*)d_in[0];
    const int*   tags  = (const int*)  d_in[1];
    const float* mask  = (const float*)d_in[2];
    const float* trans = (const float*)d_in[3];
    float* out = (float*)d_out;

    crf_mma_kernel<<<Bn/4, 128>>>(em, tags, mask, trans, out);
}